// round 4
// baseline (speedup 1.0000x reference)
#include <cuda_runtime.h>
#include <cstdint>

#define T 24
#define D 64
#define KW 3
#define WARPS 6
#define BLOCK (WARPS * 32)
#define STRIDE 68          // padded floats per t-row; even (float2 loads), mult of 4 (float4 stores)

// Folded weights: g_M[k][i][o2] = sum_o W_lin[o2,o] * W_conv[o,i,0,k]  (o2-contiguous -> f32 pairs)
__device__ float g_M[KW * D * D];
__device__ float g_c[D];   // c[o2] = sum_o W_lin[o2,o] * b_conv[o]

__global__ void prep_kernel(const float* __restrict__ W_conv,
                            const float* __restrict__ b_conv,
                            const float* __restrict__ W_lin) {
    int gid = blockIdx.x * blockDim.x + threadIdx.x;
    if (gid < KW * D * D) {
        int k   = gid / (D * D);
        int rem = gid % (D * D);
        int i   = rem / D;
        int o2  = rem % D;
        float s = 0.f;
#pragma unroll 8
        for (int o = 0; o < D; ++o)
            s += W_lin[o2 * D + o] * W_conv[o * (D * KW) + i * KW + k];
        g_M[gid] = s;
    }
    if (gid < D) {
        float s = 0.f;
#pragma unroll 8
        for (int o = 0; o < D; ++o) s += W_lin[gid * D + o] * b_conv[o];
        g_c[gid] = s;
    }
}

__device__ __forceinline__ uint64_t pack2(float x) {
    uint64_t d;
    asm("mov.b64 %0, {%1, %1};" : "=l"(d) : "f"(x));
    return d;
}
__device__ __forceinline__ void fma2(uint64_t& a, uint64_t m, uint64_t v) {
    asm("fma.rn.f32x2 %0, %1, %2, %0;" : "+l"(a) : "l"(m), "l"(v));
}
__device__ __forceinline__ float2 as_f2(uint64_t x) {
    float2 f;
    asm("mov.b64 {%0, %1}, %2;" : "=f"(f.x), "=f"(f.y) : "l"(x));
    return f;
}

__global__ __launch_bounds__(BLOCK, 3)
void temporal_agg_kernel(const float* __restrict__ val,
                         const float* __restrict__ b_lin,
                         float* __restrict__ out,
                         int rows_total) {
    __shared__ float sval[WARPS][26 * STRIDE];  // padded: rows 0 and 25 are zero halo

    const int warp = threadIdx.x >> 5;
    const int lane = threadIdx.x & 31;
    const int tg   = lane >> 3;        // 0..3 -> t-tile of 6
    const int o2g  = lane & 7;         // 0..7 -> 8 channels (4 f32 pairs)
    const int tbase  = tg * 6;
    const int o2base = o2g * 8;

    const int row = blockIdx.x * WARPS + warp;
    if (row >= rows_total) return;     // warp-uniform exit

    float* sv = sval[warp];

    // zero halo rows (padded t = 0 and 25)
    for (int i = lane; i < D; i += 32) {
        sv[i] = 0.f;
        sv[25 * STRIDE + i] = 0.f;
    }
    // stage this warp's row: 1536 floats as float4, coalesced LDG.128
    {
        const float4* src = (const float4*)(val + (size_t)row * (T * D));
#pragma unroll
        for (int idx = lane; idx < (T * D) / 4; idx += 32) {
            float4 x = src[idx];
            int e = idx * 4;
            int t = e >> 6, i = e & 63;
            *(float4*)(sv + (t + 1) * STRIDE + i) = x;   // 16B aligned: STRIDE%4==0
        }
    }
    __syncwarp();

    // acc[t6][p]: f32x2 over channels (o2base+2p, o2base+2p+1), t = tbase+t6
    uint64_t acc[6][4];
#pragma unroll
    for (int t6 = 0; t6 < 6; ++t6)
#pragma unroll
        for (int p = 0; p < 4; ++p) acc[t6][p] = 0ull;

    const float* vb = sv + tbase * STRIDE;  // padded row tbase == logical t-1 of tile start

#pragma unroll 1
    for (int i2 = 0; i2 < D; i2 += 2) {
        // value loads: one LDS.64 per j covers i2 and i2+1 (4 distinct addrs/warp, conflict-free)
        uint64_t vlo[8], vhi[8];
#pragma unroll
        for (int j = 0; j < 8; ++j) {
            float2 v2 = *(const float2*)(vb + j * STRIDE + i2);
            vlo[j] = pack2(v2.x);
            vhi[j] = pack2(v2.y);
        }

#pragma unroll
        for (int s = 0; s < 2; ++s) {
            const int i = i2 + s;
            const uint64_t* vv = s ? vhi : vlo;

            // 6 LDG.128 weight loads (2 pairs each), L1/L2-resident
            ulonglong2 mm[KW][2];
#pragma unroll
            for (int k = 0; k < KW; ++k)
#pragma unroll
                for (int p2 = 0; p2 < 2; ++p2)
                    mm[k][p2] = __ldg((const ulonglong2*)g_M +
                                      (size_t)((k * D + i) * 16 + o2g * 2 + p2));

            // 72 FFMA2 = 144 FMA
#pragma unroll
            for (int k = 0; k < KW; ++k)
#pragma unroll
                for (int t6 = 0; t6 < 6; ++t6) {
                    fma2(acc[t6][0], mm[k][0].x, vv[t6 + k]);
                    fma2(acc[t6][1], mm[k][0].y, vv[t6 + k]);
                    fma2(acc[t6][2], mm[k][1].x, vv[t6 + k]);
                    fma2(acc[t6][3], mm[k][1].y, vv[t6 + k]);
                }
        }
    }

    // cross-tile band neighbors via shuffle: g[tbase-1] from tg-1 (acc[5]), g[tbase+6] from tg+1 (acc[0])
    const unsigned FULL = 0xffffffffu;
    uint64_t up[4], dn[4];
#pragma unroll
    for (int p = 0; p < 4; ++p) {
        up[p] = __shfl_sync(FULL, acc[5][p], (lane - 8) & 31);
        dn[p] = __shfl_sync(FULL, acc[0][p], (lane + 8) & 31);
    }

    // per-channel combined biases
    float b3[8], b2[8];
#pragma unroll
    for (int c = 0; c < 8; ++c) {
        float cc = g_c[o2base + c];
        float bl = __ldg(b_lin + o2base + c);
        b3[c] = fmaf(3.f, cc, bl);
        b2[c] = fmaf(2.f, cc, bl);
    }

    float* orow = out + (size_t)row * (T * D) + o2base;
#pragma unroll
    for (int t6 = 0; t6 < 6; ++t6) {
        const int t = tbase + t6;
        float r[8];
#pragma unroll
        for (int p = 0; p < 4; ++p) {
            uint64_t pr = (t6 > 0) ? acc[t6 - 1][p] : ((tg > 0) ? up[p] : 0ull);
            uint64_t nx = (t6 < 5) ? acc[t6 + 1][p] : ((tg < 3) ? dn[p] : 0ull);
            float2 a = as_f2(acc[t6][p]);
            float2 q = as_f2(pr);
            float2 w = as_f2(nx);
            float z0 = a.x + q.x + w.x;
            float z1 = a.y + q.y + w.y;
            const bool edge = (t == 0) || (t == T - 1);
            r[2 * p]     = fmaxf(z0 + (edge ? b2[2 * p]     : b3[2 * p]),     0.f);
            r[2 * p + 1] = fmaxf(z1 + (edge ? b2[2 * p + 1] : b3[2 * p + 1]), 0.f);
        }
        float4* o4 = (float4*)(orow + t * D);
        o4[0] = make_float4(r[0], r[1], r[2], r[3]);
        o4[1] = make_float4(r[4], r[5], r[6], r[7]);
    }
}

extern "C" void kernel_launch(void* const* d_in, const int* in_sizes, int n_in,
                              void* d_out, int out_size) {
    const float* value  = (const float*)d_in[0];
    const float* W_conv = (const float*)d_in[1];
    const float* b_conv = (const float*)d_in[2];
    const float* W_lin  = (const float*)d_in[3];
    const float* b_lin  = (const float*)d_in[4];
    float* out = (float*)d_out;

    const int rows_total = in_sizes[0] / (T * D);   // B*N = 16384

    prep_kernel<<<(KW * D * D + 255) / 256, 256>>>(W_conv, b_conv, W_lin);

    const int grid = (rows_total + WARPS - 1) / WARPS;
    temporal_agg_kernel<<<grid, BLOCK>>>(value, b_lin, out, rows_total);
}